// round 12
// baseline (speedup 1.0000x reference)
#include <cuda_runtime.h>
#include <math.h>
#include <string.h>

// Problem constants
#define Bn  8
#define Hn  512
#define Wn  512
#define KK  5
#define NK  25      // KK*KK
#define HIDc 32
#define OC  50      // 2*NK

#define HW (Hn*Wn)

// Tile config: 32x8 pixel tile, 32x4 threads, 2 vertical pixels per thread.
#define TX 32
#define TYT 4
#define TYP 8
#define NTHREADS (TX*TYT)  // 128

#define GW (TX + 2)
#define GH (TYP + 2)
#define FW (TX + 4)
#define FH (TYP + 4)

typedef unsigned long long u64;

// ---------------------------------------------------------------------------
// packed f32x2 helpers
// ---------------------------------------------------------------------------
__device__ __forceinline__ u64 pk2(float lo, float hi) {
    u64 r;
    asm("mov.b64 %0, {%1,%2};" : "=l"(r) : "f"(lo), "f"(hi));
    return r;
}
__device__ __forceinline__ u64 fma2(u64 a, u64 b, u64 c) {
    u64 d;
    asm("fma.rn.f32x2 %0, %1, %2, %3;" : "=l"(d) : "l"(a), "l"(b), "l"(c));
    return d;
}
// MOV-free reinterpret of a 64-bit pair as two floats
__device__ __forceinline__ float2 as_f2(u64 v) {
    float2 f;
    memcpy(&f, &v, 8);
    return f;
}

// ---------------------------------------------------------------------------
// Single fused kernel:
//   per-tile guidance (bilinear grid-sample warp + fb + exp weight, recomputed
//   with halo) -> conv3x3(3->32)+ReLU -> conv1x1(32->50) as direct-form
//   hidden-channel-pair FFMA2 -> dynamic 5x5 kernel apply.
// 2 pixels per thread; all heavy fma2 operands MOV-free from smem/registers.
// Occupancy target 6 blocks/SM (~85 regs) for latency hiding.
// ---------------------------------------------------------------------------
__global__ __launch_bounds__(NTHREADS, 6)
void refine_kernel(const float* __restrict__ v02,
                   const float* __restrict__ v20,
                   const float* __restrict__ w1,
                   const float* __restrict__ b1,
                   const float* __restrict__ w2,
                   const float* __restrict__ b2,
                   float* __restrict__ out)
{
    // W1 interleaved channel pairs: [c][jp][10 s-pairs]; pair s = (w1[2jp][c][s], w1[2jp+1][c][s])
    __shared__ __align__(16) float sW1p[3 * 16 * 20];
    __shared__ __align__(8)  float sB1p[HIDc];          // (b1[2jp],b1[2jp+1])
    // W2 plain row-major copy [50][32] — adjacent c's form the fma2 pairs
    __shared__ __align__(16) float sW2[OC * HIDc];
    // Bias pairs (b2[k], 0) for chain init
    __shared__ __align__(8) u64 sB2z[OC];
    // Guidance tile, DUPLICATED pairs (g,g): [3][GH][GW]
    __shared__ __align__(8) u64 sGp[3 * GH * GW];
    // Flow tile, channel pairs (flow0,flow1): [FH][FW]
    __shared__ __align__(8) u64 sFp[FH * FW];

    const int tid = threadIdx.y * TX + threadIdx.x;
    const int bx = blockIdx.x * TX;
    const int by = blockIdx.y * TYP;
    const int b  = blockIdx.z;

    // --- stage W1 pairs ---  w1 global: [j][c][s] -> j*27 + c*9 + s
    for (int i = tid; i < 3 * 16 * 10; i += NTHREADS) {
        int s  = i % 10;
        int jp = (i / 10) % 16;
        int c  = i / 160;
        float lo = 0.0f, hi = 0.0f;
        if (s < 9) {
            lo = w1[(2 * jp) * 27 + c * 9 + s];
            hi = w1[(2 * jp + 1) * 27 + c * 9 + s];
        }
        sW1p[i * 2]     = lo;
        sW1p[i * 2 + 1] = hi;
    }
    if (tid < 16) {
        sB1p[tid * 2]     = b1[2 * tid];
        sB1p[tid * 2 + 1] = b1[2 * tid + 1];
    }
    // --- stage W2: plain copy (vectorized) ---
    {
        const float4* src = (const float4*)w2;
        float4* dst = (float4*)sW2;
        for (int i = tid; i < OC * HIDc / 4; i += NTHREADS)
            dst[i] = src[i];
    }
    if (tid < OC) sB2z[tid] = pk2(b2[tid], 0.0f);

    const float* v02b = v02 + b * 2 * HW;
    const float* v20b = v20 + b * 2 * HW;

    // --- compute guidance inline for the halo-1 tile (zero OOB = conv pad) ---
    for (int i = tid; i < GH * GW; i += NTHREADS) {
        int yy = i / GW;
        int xx = i - yy * GW;
        int gyy = by + yy - 1;
        int gxx = bx + xx - 1;
        float fb0 = 0.0f, fb1 = 0.0f, wv = 0.0f;
        if (gyy >= 0 && gyy < Hn && gxx >= 0 && gxx < Wn) {
            float f0 = v02b[gyy * Wn + gxx];
            float f1 = v02b[HW + gyy * Wn + gxx];

            float gx = -1.0f + 2.0f * (float)gxx / (float)(Wn - 1);
            float gy = -1.0f + 2.0f * (float)gyy / (float)(Hn - 1);
            float sgx = gx + f0 / (Wn * 0.5f);
            float sgy = gy + f1 / (Hn * 0.5f);

            float ixf = (sgx + 1.0f) * 0.5f * (float)(Wn - 1);
            float iyf = (sgy + 1.0f) * 0.5f * (float)(Hn - 1);

            float x0f = floorf(ixf);
            float y0f = floorf(iyf);
            int   x0  = (int)x0f;
            int   y0  = (int)y0f;
            float wx1 = ixf - x0f;
            float wy1 = iyf - y0f;
            float wx0 = 1.0f - wx1;
            float wy0 = 1.0f - wy1;

            float s0 = 0.0f, s1 = 0.0f;
#pragma unroll
            for (int cy = 0; cy < 2; cy++) {
                int   yc = y0 + cy;
                float wy = cy ? wy1 : wy0;
                bool  vy = (yc >= 0) && (yc <= Hn - 1);
                int   yi = min(max(yc, 0), Hn - 1);
#pragma unroll
                for (int cx = 0; cx < 2; cx++) {
                    int   xc = x0 + cx;
                    float wx = cx ? wx1 : wx0;
                    bool  vx = (xc >= 0) && (xc <= Wn - 1);
                    int   xi = min(max(xc, 0), Wn - 1);
                    float wgt = (vx && vy) ? (wx * wy) : 0.0f;
                    s0 += wgt * v20b[yi * Wn + xi];
                    s1 += wgt * v20b[HW + yi * Wn + xi];
                }
            }
            fb0 = f0 + s0;
            fb1 = f1 + s1;
            float cons = sqrtf(fb0 * fb0 + fb1 * fb1);
            wv = __expf(-cons);
        }
        sGp[0 * (GH * GW) + i] = pk2(fb0, fb0);
        sGp[1 * (GH * GW) + i] = pk2(fb1, fb1);
        sGp[2 * (GH * GW) + i] = pk2(wv, wv);
    }

    // --- stage flow tile as channel pairs (zero OOB = unfold padding) ---
    for (int i = tid; i < FH * FW; i += NTHREADS) {
        int yy = i / FW;
        int xx = i - yy * FW;
        int gyy = by + yy - 2;
        int gxx = bx + xx - 2;
        float f0 = 0.0f, f1 = 0.0f;
        if (gyy >= 0 && gyy < Hn && gxx >= 0 && gxx < Wn) {
            f0 = v02b[gyy * Wn + gxx];
            f1 = v02b[HW + gyy * Wn + gxx];
        }
        sFp[i] = pk2(f0, f1);
    }

    __syncthreads();

    const int lx = threadIdx.x;
    const int py = threadIdx.y * 2;   // tile-local row of pixel0 (pixel1 = py+1)

    // --- conv3x3: A0[jp] = (h[2jp],h[2jp+1]) for pixel0; A1 for pixel1 ---
    u64 A0[16], A1[16];
    {
        const u64* bp = (const u64*)sB1p;
#pragma unroll
        for (int jp = 0; jp < 16; jp++) { A0[jp] = bp[jp]; A1[jp] = bp[jp]; }
    }

#pragma unroll
    for (int c = 0; c < 3; c++) {
        // duplicated taps: 4 rows x 3 cols union of both pixels (direct LDS.64)
        u64 gd[12];
#pragma unroll
        for (int dy = 0; dy < 4; dy++)
#pragma unroll
            for (int dx = 0; dx < 3; dx++)
                gd[dy * 3 + dx] = sGp[c * (GH * GW) + (py + dy) * GW + (lx + dx)];

#pragma unroll
        for (int jp = 0; jp < 16; jp++) {
            const float* base = sW1p + (c * 16 + jp) * 20;
            ulonglong2 wA = *(const ulonglong2*)(base);        // s0,s1
            ulonglong2 wB = *(const ulonglong2*)(base + 4);    // s2,s3
            ulonglong2 wC = *(const ulonglong2*)(base + 8);    // s4,s5
            ulonglong2 wD = *(const ulonglong2*)(base + 12);   // s6,s7
            u64        wE = *(const u64*)(base + 16);          // s8
            A0[jp] = fma2(wA.x, gd[0], A0[jp]);  A1[jp] = fma2(wA.x, gd[3], A1[jp]);
            A0[jp] = fma2(wA.y, gd[1], A0[jp]);  A1[jp] = fma2(wA.y, gd[4], A1[jp]);
            A0[jp] = fma2(wB.x, gd[2], A0[jp]);  A1[jp] = fma2(wB.x, gd[5], A1[jp]);
            A0[jp] = fma2(wB.y, gd[3], A0[jp]);  A1[jp] = fma2(wB.y, gd[6], A1[jp]);
            A0[jp] = fma2(wC.x, gd[4], A0[jp]);  A1[jp] = fma2(wC.x, gd[7], A1[jp]);
            A0[jp] = fma2(wC.y, gd[5], A0[jp]);  A1[jp] = fma2(wC.y, gd[8], A1[jp]);
            A0[jp] = fma2(wD.x, gd[6], A0[jp]);  A1[jp] = fma2(wD.x, gd[9], A1[jp]);
            A0[jp] = fma2(wD.y, gd[7], A0[jp]);  A1[jp] = fma2(wD.y, gd[10], A1[jp]);
            A0[jp] = fma2(wE,   gd[8], A0[jp]);  A1[jp] = fma2(wE,   gd[11], A1[jp]);
        }
    }

    // ReLU halves IN PLACE: A becomes hp = (relu lo, relu hi)
#pragma unroll
    for (int jp = 0; jp < 16; jp++) {
        float2 a = as_f2(A0[jp]);
        A0[jp] = pk2(fmaxf(a.x, 0.0f), fmaxf(a.y, 0.0f));
        float2 bb = as_f2(A1[jp]);
        A1[jp] = pk2(fmaxf(bb.x, 0.0f), fmaxf(bb.y, 0.0f));
    }

    // --- 1x1 conv (direct form) + dynamic-kernel apply ---
    // ker(k,px) = b2[k] + w2[k,:].h(px);  out_ch(px) += ker(k,px) * patch
    float o00 = 0.0f, o10 = 0.0f;   // pixel0: ch0, ch1
    float o01 = 0.0f, o11 = 0.0f;   // pixel1: ch0, ch1

#pragma unroll 1
    for (int ki = 0; ki < KK; ki++) {
#pragma unroll
        for (int kj = 0; kj < KK; kj++) {
            int k = ki * KK + kj;
            // chains init = (b2, 0); horizontal add merges bias at the end
            u64 t00 = sB2z[k],      t01 = t00;   // ch0: px0, px1
            u64 t10 = sB2z[NK + k], t11 = t10;   // ch1: px0, px1

            const ulonglong2* w0 = (const ulonglong2*)(sW2 + k * HIDc);
            const ulonglong2* w1r = (const ulonglong2*)(sW2 + (NK + k) * HIDc);
#pragma unroll
            for (int q = 0; q < 8; q++) {      // pairs 2q, 2q+1
                ulonglong2 wa = w0[q];
                ulonglong2 wb = w1r[q];
                t00 = fma2(wa.x, A0[2 * q], t00);
                t01 = fma2(wa.x, A1[2 * q], t01);
                t10 = fma2(wb.x, A0[2 * q], t10);
                t11 = fma2(wb.x, A1[2 * q], t11);
                t00 = fma2(wa.y, A0[2 * q + 1], t00);
                t01 = fma2(wa.y, A1[2 * q + 1], t01);
                t10 = fma2(wb.y, A0[2 * q + 1], t10);
                t11 = fma2(wb.y, A1[2 * q + 1], t11);
            }

            float2 a00 = as_f2(t00);
            float2 a01 = as_f2(t01);
            float2 a10 = as_f2(t10);
            float2 a11 = as_f2(t11);
            float ker00 = a00.x + a00.y;   // ch0, px0 (bias included)
            float ker01 = a01.x + a01.y;   // ch0, px1
            float ker10 = a10.x + a10.y;   // ch1, px0
            float ker11 = a11.x + a11.y;   // ch1, px1

            float2 p0 = as_f2(sFp[(py + ki) * FW + (lx + kj)]);       // (flow0,flow1) px0
            float2 p1 = as_f2(sFp[(py + 1 + ki) * FW + (lx + kj)]);   // px1
            o00 = fmaf(ker00, p0.x, o00);
            o10 = fmaf(ker10, p0.y, o10);
            o01 = fmaf(ker01, p1.x, o01);
            o11 = fmaf(ker11, p1.y, o11);
        }
    }

    int oy = by + py;
    int ox = bx + lx;
    float* ob = out + b * 2 * HW;
    ob[oy * Wn + ox]            = o00;
    ob[HW + oy * Wn + ox]       = o10;
    ob[(oy + 1) * Wn + ox]      = o01;
    ob[HW + (oy + 1) * Wn + ox] = o11;
}

// ---------------------------------------------------------------------------
// Launch
// ---------------------------------------------------------------------------
extern "C" void kernel_launch(void* const* d_in, const int* in_sizes, int n_in,
                              void* d_out, int out_size)
{
    const float* v02 = (const float*)d_in[0];
    const float* v20 = (const float*)d_in[1];
    const float* w1  = (const float*)d_in[2];
    const float* b1  = (const float*)d_in[3];
    const float* w2  = (const float*)d_in[4];
    const float* b2  = (const float*)d_in[5];
    float* out = (float*)d_out;

    dim3 block(TX, TYT, 1);
    dim3 grid(Wn / TX, Hn / TYP, Bn);
    refine_kernel<<<grid, block>>>(v02, v20, w1, b1, w2, b2, out);
}

// round 13
// speedup vs baseline: 1.1906x; 1.1906x over previous
#include <cuda_runtime.h>
#include <math.h>
#include <string.h>

// Problem constants
#define Bn  8
#define Hn  512
#define Wn  512
#define KK  5
#define NK  25      // KK*KK
#define HIDc 32
#define OC  50      // 2*NK

#define HW (Hn*Wn)

// Tile config: 32x8 pixel tile, 32x4 threads, 2 vertical pixels per thread.
#define TX 32
#define TYT 4
#define TYP 8
#define NTHREADS (TX*TYT)  // 128

#define GW (TX + 2)
#define GH (TYP + 2)
#define FW (TX + 4)
#define FH (TYP + 4)

typedef unsigned long long u64;

// ---------------------------------------------------------------------------
// packed f32x2 helpers
// ---------------------------------------------------------------------------
__device__ __forceinline__ u64 pk2(float lo, float hi) {
    u64 r;
    asm("mov.b64 %0, {%1,%2};" : "=l"(r) : "f"(lo), "f"(hi));
    return r;
}
__device__ __forceinline__ u64 fma2(u64 a, u64 b, u64 c) {
    u64 d;
    asm("fma.rn.f32x2 %0, %1, %2, %3;" : "=l"(d) : "l"(a), "l"(b), "l"(c));
    return d;
}
// MOV-free reinterpret of a 64-bit pair as two floats
__device__ __forceinline__ float2 as_f2(u64 v) {
    float2 f;
    memcpy(&f, &v, 8);
    return f;
}

// ---------------------------------------------------------------------------
// Single fused kernel:
//   per-tile guidance (bilinear grid-sample warp + fb + exp weight, recomputed
//   with halo) -> conv3x3(3->32)+ReLU -> conv1x1(32->50) as direct-form
//   hidden-channel-pair FFMA2 -> dynamic 5x5 kernel apply with PACKED output
//   accumulators (horizontal add deferred to the end).
// 2 pixels per thread; all heavy fma2 operands MOV-free from smem/registers.
// Occupancy 5 blocks/SM (96-100 regs) — proven optimum; occ-6 spills.
// ---------------------------------------------------------------------------
__global__ __launch_bounds__(NTHREADS, 5)
void refine_kernel(const float* __restrict__ v02,
                   const float* __restrict__ v20,
                   const float* __restrict__ w1,
                   const float* __restrict__ b1,
                   const float* __restrict__ w2,
                   const float* __restrict__ b2,
                   float* __restrict__ out)
{
    // W1 interleaved channel pairs: [c][jp][10 s-pairs]; pair s = (w1[2jp][c][s], w1[2jp+1][c][s])
    __shared__ __align__(16) float sW1p[3 * 16 * 20];
    __shared__ __align__(8)  float sB1p[HIDc];          // (b1[2jp],b1[2jp+1])
    // W2 plain row-major copy [50][32] — adjacent c's form the fma2 pairs
    __shared__ __align__(16) float sW2[OC * HIDc];
    // Bias pairs (b2[k], 0) for chain init
    __shared__ __align__(8) u64 sB2z[OC];
    // Guidance tile, DUPLICATED pairs (g,g): [3][GH][GW]
    __shared__ __align__(8) u64 sGp[3 * GH * GW];
    // Flow tile, DUPLICATED per channel: (f0,f0) and (f1,f1): [FH][FW] each
    __shared__ __align__(8) u64 sFd0[FH * FW];
    __shared__ __align__(8) u64 sFd1[FH * FW];

    const int tid = threadIdx.y * TX + threadIdx.x;
    const int bx = blockIdx.x * TX;
    const int by = blockIdx.y * TYP;
    const int b  = blockIdx.z;

    // --- stage W1 pairs ---  w1 global: [j][c][s] -> j*27 + c*9 + s
    for (int i = tid; i < 3 * 16 * 10; i += NTHREADS) {
        int s  = i % 10;
        int jp = (i / 10) % 16;
        int c  = i / 160;
        float lo = 0.0f, hi = 0.0f;
        if (s < 9) {
            lo = w1[(2 * jp) * 27 + c * 9 + s];
            hi = w1[(2 * jp + 1) * 27 + c * 9 + s];
        }
        sW1p[i * 2]     = lo;
        sW1p[i * 2 + 1] = hi;
    }
    if (tid < 16) {
        sB1p[tid * 2]     = b1[2 * tid];
        sB1p[tid * 2 + 1] = b1[2 * tid + 1];
    }
    // --- stage W2: plain copy (vectorized) ---
    {
        const float4* src = (const float4*)w2;
        float4* dst = (float4*)sW2;
        for (int i = tid; i < OC * HIDc / 4; i += NTHREADS)
            dst[i] = src[i];
    }
    if (tid < OC) sB2z[tid] = pk2(b2[tid], 0.0f);

    const float* v02b = v02 + b * 2 * HW;
    const float* v20b = v20 + b * 2 * HW;

    // --- compute guidance inline for the halo-1 tile (zero OOB = conv pad) ---
    for (int i = tid; i < GH * GW; i += NTHREADS) {
        int yy = i / GW;
        int xx = i - yy * GW;
        int gyy = by + yy - 1;
        int gxx = bx + xx - 1;
        float fb0 = 0.0f, fb1 = 0.0f, wv = 0.0f;
        if (gyy >= 0 && gyy < Hn && gxx >= 0 && gxx < Wn) {
            float f0 = v02b[gyy * Wn + gxx];
            float f1 = v02b[HW + gyy * Wn + gxx];

            float gx = -1.0f + 2.0f * (float)gxx / (float)(Wn - 1);
            float gy = -1.0f + 2.0f * (float)gyy / (float)(Hn - 1);
            float sgx = gx + f0 / (Wn * 0.5f);
            float sgy = gy + f1 / (Hn * 0.5f);

            float ixf = (sgx + 1.0f) * 0.5f * (float)(Wn - 1);
            float iyf = (sgy + 1.0f) * 0.5f * (float)(Hn - 1);

            float x0f = floorf(ixf);
            float y0f = floorf(iyf);
            int   x0  = (int)x0f;
            int   y0  = (int)y0f;
            float wx1 = ixf - x0f;
            float wy1 = iyf - y0f;
            float wx0 = 1.0f - wx1;
            float wy0 = 1.0f - wy1;

            float s0 = 0.0f, s1 = 0.0f;
#pragma unroll
            for (int cy = 0; cy < 2; cy++) {
                int   yc = y0 + cy;
                float wy = cy ? wy1 : wy0;
                bool  vy = (yc >= 0) && (yc <= Hn - 1);
                int   yi = min(max(yc, 0), Hn - 1);
#pragma unroll
                for (int cx = 0; cx < 2; cx++) {
                    int   xc = x0 + cx;
                    float wx = cx ? wx1 : wx0;
                    bool  vx = (xc >= 0) && (xc <= Wn - 1);
                    int   xi = min(max(xc, 0), Wn - 1);
                    float wgt = (vx && vy) ? (wx * wy) : 0.0f;
                    s0 += wgt * v20b[yi * Wn + xi];
                    s1 += wgt * v20b[HW + yi * Wn + xi];
                }
            }
            fb0 = f0 + s0;
            fb1 = f1 + s1;
            float cons = sqrtf(fb0 * fb0 + fb1 * fb1);
            wv = __expf(-cons);
        }
        sGp[0 * (GH * GW) + i] = pk2(fb0, fb0);
        sGp[1 * (GH * GW) + i] = pk2(fb1, fb1);
        sGp[2 * (GH * GW) + i] = pk2(wv, wv);
    }

    // --- stage flow tile duplicated per channel (zero OOB = unfold pad) ---
    for (int i = tid; i < FH * FW; i += NTHREADS) {
        int yy = i / FW;
        int xx = i - yy * FW;
        int gyy = by + yy - 2;
        int gxx = bx + xx - 2;
        float f0 = 0.0f, f1 = 0.0f;
        if (gyy >= 0 && gyy < Hn && gxx >= 0 && gxx < Wn) {
            f0 = v02b[gyy * Wn + gxx];
            f1 = v02b[HW + gyy * Wn + gxx];
        }
        sFd0[i] = pk2(f0, f0);
        sFd1[i] = pk2(f1, f1);
    }

    __syncthreads();

    const int lx = threadIdx.x;
    const int py = threadIdx.y * 2;   // tile-local row of pixel0 (pixel1 = py+1)

    // --- conv3x3: A0[jp] = (h[2jp],h[2jp+1]) for pixel0; A1 for pixel1 ---
    u64 A0[16], A1[16];
    {
        const u64* bp = (const u64*)sB1p;
#pragma unroll
        for (int jp = 0; jp < 16; jp++) { A0[jp] = bp[jp]; A1[jp] = bp[jp]; }
    }

#pragma unroll
    for (int c = 0; c < 3; c++) {
        // duplicated taps: 4 rows x 3 cols union of both pixels (direct LDS.64)
        u64 gd[12];
#pragma unroll
        for (int dy = 0; dy < 4; dy++)
#pragma unroll
            for (int dx = 0; dx < 3; dx++)
                gd[dy * 3 + dx] = sGp[c * (GH * GW) + (py + dy) * GW + (lx + dx)];

#pragma unroll
        for (int jp = 0; jp < 16; jp++) {
            const float* base = sW1p + (c * 16 + jp) * 20;
            ulonglong2 wA = *(const ulonglong2*)(base);        // s0,s1
            ulonglong2 wB = *(const ulonglong2*)(base + 4);    // s2,s3
            ulonglong2 wC = *(const ulonglong2*)(base + 8);    // s4,s5
            ulonglong2 wD = *(const ulonglong2*)(base + 12);   // s6,s7
            u64        wE = *(const u64*)(base + 16);          // s8
            A0[jp] = fma2(wA.x, gd[0], A0[jp]);  A1[jp] = fma2(wA.x, gd[3], A1[jp]);
            A0[jp] = fma2(wA.y, gd[1], A0[jp]);  A1[jp] = fma2(wA.y, gd[4], A1[jp]);
            A0[jp] = fma2(wB.x, gd[2], A0[jp]);  A1[jp] = fma2(wB.x, gd[5], A1[jp]);
            A0[jp] = fma2(wB.y, gd[3], A0[jp]);  A1[jp] = fma2(wB.y, gd[6], A1[jp]);
            A0[jp] = fma2(wC.x, gd[4], A0[jp]);  A1[jp] = fma2(wC.x, gd[7], A1[jp]);
            A0[jp] = fma2(wC.y, gd[5], A0[jp]);  A1[jp] = fma2(wC.y, gd[8], A1[jp]);
            A0[jp] = fma2(wD.x, gd[6], A0[jp]);  A1[jp] = fma2(wD.x, gd[9], A1[jp]);
            A0[jp] = fma2(wD.y, gd[7], A0[jp]);  A1[jp] = fma2(wD.y, gd[10], A1[jp]);
            A0[jp] = fma2(wE,   gd[8], A0[jp]);  A1[jp] = fma2(wE,   gd[11], A1[jp]);
        }
    }

    // ReLU halves IN PLACE: A becomes hp = (relu lo, relu hi)
#pragma unroll
    for (int jp = 0; jp < 16; jp++) {
        float2 a = as_f2(A0[jp]);
        A0[jp] = pk2(fmaxf(a.x, 0.0f), fmaxf(a.y, 0.0f));
        float2 bb = as_f2(A1[jp]);
        A1[jp] = pk2(fmaxf(bb.x, 0.0f), fmaxf(bb.y, 0.0f));
    }

    // --- 1x1 conv (direct form) + dynamic-kernel apply, packed outputs ---
    // t_k = (partial ker sums over paired c) with bias in the lo half.
    // out_ch = hadd( sum_k t_k (.) (p_k, p_k) )  — horizontal add deferred.
    u64 O00 = 0ull, O10 = 0ull;   // pixel0: ch0, ch1 (packed partial sums)
    u64 O01 = 0ull, O11 = 0ull;   // pixel1: ch0, ch1

#pragma unroll 1
    for (int ki = 0; ki < KK; ki++) {
#pragma unroll
        for (int kj = 0; kj < KK; kj++) {
            int k = ki * KK + kj;
            // chains init = (b2, 0)
            u64 t00 = sB2z[k],      t01 = t00;   // ch0: px0, px1
            u64 t10 = sB2z[NK + k], t11 = t10;   // ch1: px0, px1

            const ulonglong2* w0 = (const ulonglong2*)(sW2 + k * HIDc);
            const ulonglong2* w1r = (const ulonglong2*)(sW2 + (NK + k) * HIDc);
#pragma unroll
            for (int q = 0; q < 8; q++) {      // pairs 2q, 2q+1
                ulonglong2 wa = w0[q];
                ulonglong2 wb = w1r[q];
                t00 = fma2(wa.x, A0[2 * q], t00);
                t01 = fma2(wa.x, A1[2 * q], t01);
                t10 = fma2(wb.x, A0[2 * q], t10);
                t11 = fma2(wb.x, A1[2 * q], t11);
                t00 = fma2(wa.y, A0[2 * q + 1], t00);
                t01 = fma2(wa.y, A1[2 * q + 1], t01);
                t10 = fma2(wb.y, A0[2 * q + 1], t10);
                t11 = fma2(wb.y, A1[2 * q + 1], t11);
            }

            // duplicated patches (p,p): direct LDS.64, no pk2
            u64 pd00 = sFd0[(py + ki) * FW + (lx + kj)];       // ch0, px0
            u64 pd10 = sFd1[(py + ki) * FW + (lx + kj)];       // ch1, px0
            u64 pd01 = sFd0[(py + 1 + ki) * FW + (lx + kj)];   // ch0, px1
            u64 pd11 = sFd1[(py + 1 + ki) * FW + (lx + kj)];   // ch1, px1
            O00 = fma2(t00, pd00, O00);
            O10 = fma2(t10, pd10, O10);
            O01 = fma2(t01, pd01, O01);
            O11 = fma2(t11, pd11, O11);
        }
    }

    // horizontal adds (once): out = O.lo + O.hi
    float2 a00 = as_f2(O00);
    float2 a10 = as_f2(O10);
    float2 a01 = as_f2(O01);
    float2 a11 = as_f2(O11);

    int oy = by + py;
    int ox = bx + lx;
    float* ob = out + b * 2 * HW;
    ob[oy * Wn + ox]            = a00.x + a00.y;
    ob[HW + oy * Wn + ox]       = a10.x + a10.y;
    ob[(oy + 1) * Wn + ox]      = a01.x + a01.y;
    ob[HW + (oy + 1) * Wn + ox] = a11.x + a11.y;
}

// ---------------------------------------------------------------------------
// Launch
// ---------------------------------------------------------------------------
extern "C" void kernel_launch(void* const* d_in, const int* in_sizes, int n_in,
                              void* d_out, int out_size)
{
    const float* v02 = (const float*)d_in[0];
    const float* v20 = (const float*)d_in[1];
    const float* w1  = (const float*)d_in[2];
    const float* b1  = (const float*)d_in[3];
    const float* w2  = (const float*)d_in[4];
    const float* b2  = (const float*)d_in[5];
    float* out = (float*)d_out;

    dim3 block(TX, TYT, 1);
    dim3 grid(Wn / TX, Hn / TYP, Bn);
    refine_kernel<<<grid, block>>>(v02, v20, w1, b1, w2, b2, out);
}

// round 14
// speedup vs baseline: 1.2867x; 1.0807x over previous
#include <cuda_runtime.h>
#include <math.h>
#include <string.h>

// Problem constants
#define Bn  8
#define Hn  512
#define Wn  512
#define KK  5
#define NK  25      // KK*KK
#define HIDc 32
#define OC  50      // 2*NK

#define HW (Hn*Wn)

// Tile config: 32x8 pixel tile, 32x4 threads, 2 vertical pixels per thread.
#define TX 32
#define TYT 4
#define TYP 8
#define NTHREADS (TX*TYT)  // 128

#define GW (TX + 2)
#define GH (TYP + 2)
#define FW (TX + 4)
#define FH (TYP + 4)

typedef unsigned long long u64;

// ---------------------------------------------------------------------------
// packed f32x2 helpers
// ---------------------------------------------------------------------------
__device__ __forceinline__ u64 pk2(float lo, float hi) {
    u64 r;
    asm("mov.b64 %0, {%1,%2};" : "=l"(r) : "f"(lo), "f"(hi));
    return r;
}
__device__ __forceinline__ u64 fma2(u64 a, u64 b, u64 c) {
    u64 d;
    asm("fma.rn.f32x2 %0, %1, %2, %3;" : "=l"(d) : "l"(a), "l"(b), "l"(c));
    return d;
}
// MOV-free reinterpret of a 64-bit pair as two floats
__device__ __forceinline__ float2 as_f2(u64 v) {
    float2 f;
    memcpy(&f, &v, 8);
    return f;
}

// ---------------------------------------------------------------------------
// Single fused kernel:
//   per-tile guidance (bilinear grid-sample warp + fb + exp weight, recomputed
//   with halo) -> conv3x3(3->32)+ReLU -> conv1x1(32->50) as direct-form
//   hidden-channel-pair FFMA2 -> dynamic 5x5 kernel apply.
// 2 pixels per thread; all heavy fma2 operands MOV-free from smem/registers.
// Occupancy 5 blocks/SM (96 regs) — proven optimum (occ-6 spills; packed
// outputs and interleaved-weight variants all measured slower).
// ---------------------------------------------------------------------------
__global__ __launch_bounds__(NTHREADS, 5)
void refine_kernel(const float* __restrict__ v02,
                   const float* __restrict__ v20,
                   const float* __restrict__ w1,
                   const float* __restrict__ b1,
                   const float* __restrict__ w2,
                   const float* __restrict__ b2,
                   float* __restrict__ out)
{
    // W1 interleaved channel pairs: [c][jp][10 s-pairs]; pair s = (w1[2jp][c][s], w1[2jp+1][c][s])
    __shared__ __align__(16) float sW1p[3 * 16 * 20];
    __shared__ __align__(8)  float sB1p[HIDc];          // (b1[2jp],b1[2jp+1])
    // W2 plain row-major copy [50][32] — adjacent c's form the fma2 pairs
    __shared__ __align__(16) float sW2[OC * HIDc];
    // Bias pairs (b2[k], 0) for chain init
    __shared__ __align__(8) u64 sB2z[OC];
    // Guidance tile, DUPLICATED pairs (g,g): [3][GH][GW]
    __shared__ __align__(8) u64 sGp[3 * GH * GW];
    // Flow tile, channel pairs (flow0,flow1): [FH][FW]
    __shared__ __align__(8) u64 sFp[FH * FW];

    const int tid = threadIdx.y * TX + threadIdx.x;
    const int bx = blockIdx.x * TX;
    const int by = blockIdx.y * TYP;
    const int b  = blockIdx.z;

    // --- stage W1 pairs ---  w1 global: [j][c][s] -> j*27 + c*9 + s
    for (int i = tid; i < 3 * 16 * 10; i += NTHREADS) {
        int s  = i % 10;
        int jp = (i / 10) % 16;
        int c  = i / 160;
        float lo = 0.0f, hi = 0.0f;
        if (s < 9) {
            lo = w1[(2 * jp) * 27 + c * 9 + s];
            hi = w1[(2 * jp + 1) * 27 + c * 9 + s];
        }
        sW1p[i * 2]     = lo;
        sW1p[i * 2 + 1] = hi;
    }
    if (tid < 16) {
        sB1p[tid * 2]     = b1[2 * tid];
        sB1p[tid * 2 + 1] = b1[2 * tid + 1];
    }
    // --- stage W2: plain copy (vectorized) ---
    {
        const float4* src = (const float4*)w2;
        float4* dst = (float4*)sW2;
        for (int i = tid; i < OC * HIDc / 4; i += NTHREADS)
            dst[i] = src[i];
    }
    if (tid < OC) sB2z[tid] = pk2(b2[tid], 0.0f);

    const float* v02b = v02 + b * 2 * HW;
    const float* v20b = v20 + b * 2 * HW;

    // --- compute guidance inline for the halo-1 tile (zero OOB = conv pad) ---
    for (int i = tid; i < GH * GW; i += NTHREADS) {
        int yy = i / GW;
        int xx = i - yy * GW;
        int gyy = by + yy - 1;
        int gxx = bx + xx - 1;
        float fb0 = 0.0f, fb1 = 0.0f, wv = 0.0f;
        if (gyy >= 0 && gyy < Hn && gxx >= 0 && gxx < Wn) {
            float f0 = v02b[gyy * Wn + gxx];
            float f1 = v02b[HW + gyy * Wn + gxx];

            float gx = -1.0f + 2.0f * (float)gxx / (float)(Wn - 1);
            float gy = -1.0f + 2.0f * (float)gyy / (float)(Hn - 1);
            float sgx = gx + f0 / (Wn * 0.5f);
            float sgy = gy + f1 / (Hn * 0.5f);

            float ixf = (sgx + 1.0f) * 0.5f * (float)(Wn - 1);
            float iyf = (sgy + 1.0f) * 0.5f * (float)(Hn - 1);

            float x0f = floorf(ixf);
            float y0f = floorf(iyf);
            int   x0  = (int)x0f;
            int   y0  = (int)y0f;
            float wx1 = ixf - x0f;
            float wy1 = iyf - y0f;
            float wx0 = 1.0f - wx1;
            float wy0 = 1.0f - wy1;

            float s0 = 0.0f, s1 = 0.0f;
#pragma unroll
            for (int cy = 0; cy < 2; cy++) {
                int   yc = y0 + cy;
                float wy = cy ? wy1 : wy0;
                bool  vy = (yc >= 0) && (yc <= Hn - 1);
                int   yi = min(max(yc, 0), Hn - 1);
#pragma unroll
                for (int cx = 0; cx < 2; cx++) {
                    int   xc = x0 + cx;
                    float wx = cx ? wx1 : wx0;
                    bool  vx = (xc >= 0) && (xc <= Wn - 1);
                    int   xi = min(max(xc, 0), Wn - 1);
                    float wgt = (vx && vy) ? (wx * wy) : 0.0f;
                    s0 += wgt * v20b[yi * Wn + xi];
                    s1 += wgt * v20b[HW + yi * Wn + xi];
                }
            }
            fb0 = f0 + s0;
            fb1 = f1 + s1;
            float cons = sqrtf(fb0 * fb0 + fb1 * fb1);
            wv = __expf(-cons);
        }
        sGp[0 * (GH * GW) + i] = pk2(fb0, fb0);
        sGp[1 * (GH * GW) + i] = pk2(fb1, fb1);
        sGp[2 * (GH * GW) + i] = pk2(wv, wv);
    }

    // --- stage flow tile as channel pairs (zero OOB = unfold padding) ---
    for (int i = tid; i < FH * FW; i += NTHREADS) {
        int yy = i / FW;
        int xx = i - yy * FW;
        int gyy = by + yy - 2;
        int gxx = bx + xx - 2;
        float f0 = 0.0f, f1 = 0.0f;
        if (gyy >= 0 && gyy < Hn && gxx >= 0 && gxx < Wn) {
            f0 = v02b[gyy * Wn + gxx];
            f1 = v02b[HW + gyy * Wn + gxx];
        }
        sFp[i] = pk2(f0, f1);
    }

    __syncthreads();

    const int lx = threadIdx.x;
    const int py = threadIdx.y * 2;   // tile-local row of pixel0 (pixel1 = py+1)

    // --- conv3x3: A0[jp] = (h[2jp],h[2jp+1]) for pixel0; A1 for pixel1 ---
    u64 A0[16], A1[16];
    {
        const u64* bp = (const u64*)sB1p;
#pragma unroll
        for (int jp = 0; jp < 16; jp++) { A0[jp] = bp[jp]; A1[jp] = bp[jp]; }
    }

#pragma unroll
    for (int c = 0; c < 3; c++) {
        // duplicated taps: 4 rows x 3 cols union of both pixels (direct LDS.64)
        u64 gd[12];
#pragma unroll
        for (int dy = 0; dy < 4; dy++)
#pragma unroll
            for (int dx = 0; dx < 3; dx++)
                gd[dy * 3 + dx] = sGp[c * (GH * GW) + (py + dy) * GW + (lx + dx)];

#pragma unroll
        for (int jp = 0; jp < 16; jp++) {
            const float* base = sW1p + (c * 16 + jp) * 20;
            ulonglong2 wA = *(const ulonglong2*)(base);        // s0,s1
            ulonglong2 wB = *(const ulonglong2*)(base + 4);    // s2,s3
            ulonglong2 wC = *(const ulonglong2*)(base + 8);    // s4,s5
            ulonglong2 wD = *(const ulonglong2*)(base + 12);   // s6,s7
            u64        wE = *(const u64*)(base + 16);          // s8
            A0[jp] = fma2(wA.x, gd[0], A0[jp]);  A1[jp] = fma2(wA.x, gd[3], A1[jp]);
            A0[jp] = fma2(wA.y, gd[1], A0[jp]);  A1[jp] = fma2(wA.y, gd[4], A1[jp]);
            A0[jp] = fma2(wB.x, gd[2], A0[jp]);  A1[jp] = fma2(wB.x, gd[5], A1[jp]);
            A0[jp] = fma2(wB.y, gd[3], A0[jp]);  A1[jp] = fma2(wB.y, gd[6], A1[jp]);
            A0[jp] = fma2(wC.x, gd[4], A0[jp]);  A1[jp] = fma2(wC.x, gd[7], A1[jp]);
            A0[jp] = fma2(wC.y, gd[5], A0[jp]);  A1[jp] = fma2(wC.y, gd[8], A1[jp]);
            A0[jp] = fma2(wD.x, gd[6], A0[jp]);  A1[jp] = fma2(wD.x, gd[9], A1[jp]);
            A0[jp] = fma2(wD.y, gd[7], A0[jp]);  A1[jp] = fma2(wD.y, gd[10], A1[jp]);
            A0[jp] = fma2(wE,   gd[8], A0[jp]);  A1[jp] = fma2(wE,   gd[11], A1[jp]);
        }
    }

    // ReLU + keep hidden vectors as pairs: hp[jp] = (relu lo, relu hi)
    u64 hp0[16], hp1[16];
#pragma unroll
    for (int jp = 0; jp < 16; jp++) {
        float2 a = as_f2(A0[jp]);
        hp0[jp] = pk2(fmaxf(a.x, 0.0f), fmaxf(a.y, 0.0f));
        float2 bb = as_f2(A1[jp]);
        hp1[jp] = pk2(fmaxf(bb.x, 0.0f), fmaxf(bb.y, 0.0f));
    }

    // --- 1x1 conv (direct form) + dynamic-kernel apply ---
    // ker(k,px) = b2[k] + w2[k,:].h(px);  out_ch(px) += ker(k,px) * patch
    float o00 = 0.0f, o10 = 0.0f;   // pixel0: ch0, ch1
    float o01 = 0.0f, o11 = 0.0f;   // pixel1: ch0, ch1

#pragma unroll 1
    for (int ki = 0; ki < KK; ki++) {
#pragma unroll
        for (int kj = 0; kj < KK; kj++) {
            int k = ki * KK + kj;
            // chains init = (b2, 0); horizontal add merges bias at the end
            u64 t00 = sB2z[k],      t01 = t00;   // ch0: px0, px1
            u64 t10 = sB2z[NK + k], t11 = t10;   // ch1: px0, px1

            const ulonglong2* w0 = (const ulonglong2*)(sW2 + k * HIDc);
            const ulonglong2* w1r = (const ulonglong2*)(sW2 + (NK + k) * HIDc);
#pragma unroll
            for (int q = 0; q < 8; q++) {      // pairs 2q, 2q+1
                ulonglong2 wa = w0[q];
                ulonglong2 wb = w1r[q];
                t00 = fma2(wa.x, hp0[2 * q], t00);
                t01 = fma2(wa.x, hp1[2 * q], t01);
                t10 = fma2(wb.x, hp0[2 * q], t10);
                t11 = fma2(wb.x, hp1[2 * q], t11);
                t00 = fma2(wa.y, hp0[2 * q + 1], t00);
                t01 = fma2(wa.y, hp1[2 * q + 1], t01);
                t10 = fma2(wb.y, hp0[2 * q + 1], t10);
                t11 = fma2(wb.y, hp1[2 * q + 1], t11);
            }

            float2 a00 = as_f2(t00);
            float2 a01 = as_f2(t01);
            float2 a10 = as_f2(t10);
            float2 a11 = as_f2(t11);
            float ker00 = a00.x + a00.y;   // ch0, px0 (bias included)
            float ker01 = a01.x + a01.y;   // ch0, px1
            float ker10 = a10.x + a10.y;   // ch1, px0
            float ker11 = a11.x + a11.y;   // ch1, px1

            float2 p0 = as_f2(sFp[(py + ki) * FW + (lx + kj)]);       // (flow0,flow1) px0
            float2 p1 = as_f2(sFp[(py + 1 + ki) * FW + (lx + kj)]);   // px1
            o00 = fmaf(ker00, p0.x, o00);
            o10 = fmaf(ker10, p0.y, o10);
            o01 = fmaf(ker01, p1.x, o01);
            o11 = fmaf(ker11, p1.y, o11);
        }
    }

    int oy = by + py;
    int ox = bx + lx;
    float* ob = out + b * 2 * HW;
    ob[oy * Wn + ox]            = o00;
    ob[HW + oy * Wn + ox]       = o10;
    ob[(oy + 1) * Wn + ox]      = o01;
    ob[HW + (oy + 1) * Wn + ox] = o11;
}

// ---------------------------------------------------------------------------
// Launch
// ---------------------------------------------------------------------------
extern "C" void kernel_launch(void* const* d_in, const int* in_sizes, int n_in,
                              void* d_out, int out_size)
{
    const float* v02 = (const float*)d_in[0];
    const float* v20 = (const float*)d_in[1];
    const float* w1  = (const float*)d_in[2];
    const float* b1  = (const float*)d_in[3];
    const float* w2  = (const float*)d_in[4];
    const float* b2  = (const float*)d_in[5];
    float* out = (float*)d_out;

    dim3 block(TX, TYT, 1);
    dim3 grid(Wn / TX, Hn / TYP, Bn);
    refine_kernel<<<grid, block>>>(v02, v20, w1, b1, w2, b2, out);
}

// round 16
// speedup vs baseline: 1.4781x; 1.1488x over previous
#include <cuda_runtime.h>
#include <math.h>
#include <string.h>

// Problem constants
#define Bn  8
#define Hn  512
#define Wn  512
#define KK  5
#define NK  25      // KK*KK
#define HIDc 32
#define OC  50      // 2*NK

#define HW (Hn*Wn)

// Tile config: 32x8 pixel tile, 32x4 threads, 2 vertical pixels per thread.
#define TX 32
#define TYT 4
#define TYP 8
#define NTHREADS (TX*TYT)  // 128

#define GW (TX + 2)
#define GH (TYP + 2)
#define FW (TX + 4)
#define FH (TYP + 4)

typedef unsigned long long u64;

// W2 in constant memory: warp-uniform reads go through the constant port,
// off-loading the L1/LSU crossbar (the measured co-bottleneck at 78%).
__constant__ __align__(16) float cW2[OC * HIDc];

// ---------------------------------------------------------------------------
// packed f32x2 helpers
// ---------------------------------------------------------------------------
__device__ __forceinline__ u64 pk2(float lo, float hi) {
    u64 r;
    asm("mov.b64 %0, {%1,%2};" : "=l"(r) : "f"(lo), "f"(hi));
    return r;
}
__device__ __forceinline__ u64 fma2(u64 a, u64 b, u64 c) {
    u64 d;
    asm("fma.rn.f32x2 %0, %1, %2, %3;" : "=l"(d) : "l"(a), "l"(b), "l"(c));
    return d;
}
// MOV-free reinterpret of a 64-bit pair as two floats
__device__ __forceinline__ float2 as_f2(u64 v) {
    float2 f;
    memcpy(&f, &v, 8);
    return f;
}

// ---------------------------------------------------------------------------
// Single fused kernel:
//   per-tile guidance (bilinear grid-sample warp + fb + exp weight, recomputed
//   with halo) -> conv3x3(3->32)+ReLU -> conv1x1(32->50) as direct-form
//   hidden-channel-pair FFMA2 (weights from CONSTANT memory) -> dynamic 5x5
//   kernel apply.
// 2 pixels per thread; all heavy fma2 operands MOV-free.
// Occupancy 5 blocks/SM (96 regs) — proven optimum.
// ---------------------------------------------------------------------------
__global__ __launch_bounds__(NTHREADS, 5)
void refine_kernel(const float* __restrict__ v02,
                   const float* __restrict__ v20,
                   const float* __restrict__ w1,
                   const float* __restrict__ b1,
                   const float* __restrict__ b2,
                   float* __restrict__ out)
{
    // W1 interleaved channel pairs: [c][jp][10 s-pairs]; pair s = (w1[2jp][c][s], w1[2jp+1][c][s])
    __shared__ __align__(16) float sW1p[3 * 16 * 20];
    __shared__ __align__(8)  float sB1p[HIDc];          // (b1[2jp],b1[2jp+1])
    // Bias pairs (b2[k], 0) for chain init
    __shared__ __align__(8) u64 sB2z[OC];
    // Guidance tile, DUPLICATED pairs (g,g): [3][GH][GW]
    __shared__ __align__(8) u64 sGp[3 * GH * GW];
    // Flow tile, channel pairs (flow0,flow1): [FH][FW]
    __shared__ __align__(8) u64 sFp[FH * FW];

    const int tid = threadIdx.y * TX + threadIdx.x;
    const int bx = blockIdx.x * TX;
    const int by = blockIdx.y * TYP;
    const int b  = blockIdx.z;

    // --- stage W1 pairs ---  w1 global: [j][c][s] -> j*27 + c*9 + s
    for (int i = tid; i < 3 * 16 * 10; i += NTHREADS) {
        int s  = i % 10;
        int jp = (i / 10) % 16;
        int c  = i / 160;
        float lo = 0.0f, hi = 0.0f;
        if (s < 9) {
            lo = w1[(2 * jp) * 27 + c * 9 + s];
            hi = w1[(2 * jp + 1) * 27 + c * 9 + s];
        }
        sW1p[i * 2]     = lo;
        sW1p[i * 2 + 1] = hi;
    }
    if (tid < 16) {
        sB1p[tid * 2]     = b1[2 * tid];
        sB1p[tid * 2 + 1] = b1[2 * tid + 1];
    }
    if (tid < OC) sB2z[tid] = pk2(b2[tid], 0.0f);

    const float* v02b = v02 + b * 2 * HW;
    const float* v20b = v20 + b * 2 * HW;

    // --- compute guidance inline for the halo-1 tile (zero OOB = conv pad) ---
    for (int i = tid; i < GH * GW; i += NTHREADS) {
        int yy = i / GW;
        int xx = i - yy * GW;
        int gyy = by + yy - 1;
        int gxx = bx + xx - 1;
        float fb0 = 0.0f, fb1 = 0.0f, wv = 0.0f;
        if (gyy >= 0 && gyy < Hn && gxx >= 0 && gxx < Wn) {
            float f0 = v02b[gyy * Wn + gxx];
            float f1 = v02b[HW + gyy * Wn + gxx];

            float gx = -1.0f + 2.0f * (float)gxx / (float)(Wn - 1);
            float gy = -1.0f + 2.0f * (float)gyy / (float)(Hn - 1);
            float sgx = gx + f0 / (Wn * 0.5f);
            float sgy = gy + f1 / (Hn * 0.5f);

            float ixf = (sgx + 1.0f) * 0.5f * (float)(Wn - 1);
            float iyf = (sgy + 1.0f) * 0.5f * (float)(Hn - 1);

            float x0f = floorf(ixf);
            float y0f = floorf(iyf);
            int   x0  = (int)x0f;
            int   y0  = (int)y0f;
            float wx1 = ixf - x0f;
            float wy1 = iyf - y0f;
            float wx0 = 1.0f - wx1;
            float wy0 = 1.0f - wy1;

            float s0 = 0.0f, s1 = 0.0f;
#pragma unroll
            for (int cy = 0; cy < 2; cy++) {
                int   yc = y0 + cy;
                float wy = cy ? wy1 : wy0;
                bool  vy = (yc >= 0) && (yc <= Hn - 1);
                int   yi = min(max(yc, 0), Hn - 1);
#pragma unroll
                for (int cx = 0; cx < 2; cx++) {
                    int   xc = x0 + cx;
                    float wx = cx ? wx1 : wx0;
                    bool  vx = (xc >= 0) && (xc <= Wn - 1);
                    int   xi = min(max(xc, 0), Wn - 1);
                    float wgt = (vx && vy) ? (wx * wy) : 0.0f;
                    s0 += wgt * v20b[yi * Wn + xi];
                    s1 += wgt * v20b[HW + yi * Wn + xi];
                }
            }
            fb0 = f0 + s0;
            fb1 = f1 + s1;
            float cons = sqrtf(fb0 * fb0 + fb1 * fb1);
            wv = __expf(-cons);
        }
        sGp[0 * (GH * GW) + i] = pk2(fb0, fb0);
        sGp[1 * (GH * GW) + i] = pk2(fb1, fb1);
        sGp[2 * (GH * GW) + i] = pk2(wv, wv);
    }

    // --- stage flow tile as channel pairs (zero OOB = unfold padding) ---
    for (int i = tid; i < FH * FW; i += NTHREADS) {
        int yy = i / FW;
        int xx = i - yy * FW;
        int gyy = by + yy - 2;
        int gxx = bx + xx - 2;
        float f0 = 0.0f, f1 = 0.0f;
        if (gyy >= 0 && gyy < Hn && gxx >= 0 && gxx < Wn) {
            f0 = v02b[gyy * Wn + gxx];
            f1 = v02b[HW + gyy * Wn + gxx];
        }
        sFp[i] = pk2(f0, f1);
    }

    __syncthreads();

    const int lx = threadIdx.x;
    const int py = threadIdx.y * 2;   // tile-local row of pixel0 (pixel1 = py+1)

    // --- conv3x3: A0[jp] = (h[2jp],h[2jp+1]) for pixel0; A1 for pixel1 ---
    u64 A0[16], A1[16];
    {
        const u64* bp = (const u64*)sB1p;
#pragma unroll
        for (int jp = 0; jp < 16; jp++) { A0[jp] = bp[jp]; A1[jp] = bp[jp]; }
    }

#pragma unroll
    for (int c = 0; c < 3; c++) {
        // duplicated taps: 4 rows x 3 cols union of both pixels (direct LDS.64)
        u64 gd[12];
#pragma unroll
        for (int dy = 0; dy < 4; dy++)
#pragma unroll
            for (int dx = 0; dx < 3; dx++)
                gd[dy * 3 + dx] = sGp[c * (GH * GW) + (py + dy) * GW + (lx + dx)];

#pragma unroll
        for (int jp = 0; jp < 16; jp++) {
            const float* base = sW1p + (c * 16 + jp) * 20;
            ulonglong2 wA = *(const ulonglong2*)(base);        // s0,s1
            ulonglong2 wB = *(const ulonglong2*)(base + 4);    // s2,s3
            ulonglong2 wC = *(const ulonglong2*)(base + 8);    // s4,s5
            ulonglong2 wD = *(const ulonglong2*)(base + 12);   // s6,s7
            u64        wE = *(const u64*)(base + 16);          // s8
            A0[jp] = fma2(wA.x, gd[0], A0[jp]);  A1[jp] = fma2(wA.x, gd[3], A1[jp]);
            A0[jp] = fma2(wA.y, gd[1], A0[jp]);  A1[jp] = fma2(wA.y, gd[4], A1[jp]);
            A0[jp] = fma2(wB.x, gd[2], A0[jp]);  A1[jp] = fma2(wB.x, gd[5], A1[jp]);
            A0[jp] = fma2(wB.y, gd[3], A0[jp]);  A1[jp] = fma2(wB.y, gd[6], A1[jp]);
            A0[jp] = fma2(wC.x, gd[4], A0[jp]);  A1[jp] = fma2(wC.x, gd[7], A1[jp]);
            A0[jp] = fma2(wC.y, gd[5], A0[jp]);  A1[jp] = fma2(wC.y, gd[8], A1[jp]);
            A0[jp] = fma2(wD.x, gd[6], A0[jp]);  A1[jp] = fma2(wD.x, gd[9], A1[jp]);
            A0[jp] = fma2(wD.y, gd[7], A0[jp]);  A1[jp] = fma2(wD.y, gd[10], A1[jp]);
            A0[jp] = fma2(wE,   gd[8], A0[jp]);  A1[jp] = fma2(wE,   gd[11], A1[jp]);
        }
    }

    // ReLU + keep hidden vectors as pairs: hp[jp] = (relu lo, relu hi)
    u64 hp0[16], hp1[16];
#pragma unroll
    for (int jp = 0; jp < 16; jp++) {
        float2 a = as_f2(A0[jp]);
        hp0[jp] = pk2(fmaxf(a.x, 0.0f), fmaxf(a.y, 0.0f));
        float2 bb = as_f2(A1[jp]);
        hp1[jp] = pk2(fmaxf(bb.x, 0.0f), fmaxf(bb.y, 0.0f));
    }

    // --- 1x1 conv (direct form, weights from CONSTANT) + 5x5 apply ---
    // ker(k,px) = b2[k] + w2[k,:].h(px);  out_ch(px) += ker(k,px) * patch
    float o00 = 0.0f, o10 = 0.0f;   // pixel0: ch0, ch1
    float o01 = 0.0f, o11 = 0.0f;   // pixel1: ch0, ch1

#pragma unroll 1
    for (int ki = 0; ki < KK; ki++) {
#pragma unroll
        for (int kj = 0; kj < KK; kj++) {
            int k = ki * KK + kj;
            // chains init = (b2, 0); horizontal add merges bias at the end
            u64 t00 = sB2z[k],      t01 = t00;   // ch0: px0, px1
            u64 t10 = sB2z[NK + k], t11 = t10;   // ch1: px0, px1

            const ulonglong2* w0 = (const ulonglong2*)(cW2 + k * HIDc);
            const ulonglong2* w1r = (const ulonglong2*)(cW2 + (NK + k) * HIDc);
#pragma unroll
            for (int q = 0; q < 8; q++) {      // pairs 2q, 2q+1
                ulonglong2 wa = w0[q];
                ulonglong2 wb = w1r[q];
                t00 = fma2(wa.x, hp0[2 * q], t00);
                t01 = fma2(wa.x, hp1[2 * q], t01);
                t10 = fma2(wb.x, hp0[2 * q], t10);
                t11 = fma2(wb.x, hp1[2 * q], t11);
                t00 = fma2(wa.y, hp0[2 * q + 1], t00);
                t01 = fma2(wa.y, hp1[2 * q + 1], t01);
                t10 = fma2(wb.y, hp0[2 * q + 1], t10);
                t11 = fma2(wb.y, hp1[2 * q + 1], t11);
            }

            float2 a00 = as_f2(t00);
            float2 a01 = as_f2(t01);
            float2 a10 = as_f2(t10);
            float2 a11 = as_f2(t11);
            float ker00 = a00.x + a00.y;   // ch0, px0 (bias included)
            float ker01 = a01.x + a01.y;   // ch0, px1
            float ker10 = a10.x + a10.y;   // ch1, px0
            float ker11 = a11.x + a11.y;   // ch1, px1

            float2 p0 = as_f2(sFp[(py + ki) * FW + (lx + kj)]);       // (flow0,flow1) px0
            float2 p1 = as_f2(sFp[(py + 1 + ki) * FW + (lx + kj)]);   // px1
            o00 = fmaf(ker00, p0.x, o00);
            o10 = fmaf(ker10, p0.y, o10);
            o01 = fmaf(ker01, p1.x, o01);
            o11 = fmaf(ker11, p1.y, o11);
        }
    }

    int oy = by + py;
    int ox = bx + lx;
    float* ob = out + b * 2 * HW;
    ob[oy * Wn + ox]            = o00;
    ob[HW + oy * Wn + ox]       = o10;
    ob[(oy + 1) * Wn + ox]      = o01;
    ob[HW + (oy + 1) * Wn + ox] = o11;
}

// ---------------------------------------------------------------------------
// Launch
// ---------------------------------------------------------------------------
extern "C" void kernel_launch(void* const* d_in, const int* in_sizes, int n_in,
                              void* d_out, int out_size)
{
    const float* v02 = (const float*)d_in[0];
    const float* v20 = (const float*)d_in[1];
    const float* w1  = (const float*)d_in[2];
    const float* b1  = (const float*)d_in[3];
    const float* w2  = (const float*)d_in[4];
    const float* b2  = (const float*)d_in[5];
    float* out = (float*)d_out;

    // Device-to-device async copy into constant memory (graph-capturable).
    cudaMemcpyToSymbolAsync(cW2, w2, OC * HIDc * sizeof(float), 0,
                            cudaMemcpyDeviceToDevice);

    dim3 block(TX, TYT, 1);
    dim3 grid(Wn / TX, Hn / TYP, Bn);
    refine_kernel<<<grid, block>>>(v02, v20, w1, b1, b2, out);
}